// round 5
// baseline (speedup 1.0000x reference)
#include <cuda_runtime.h>
#include <cuda_bf16.h>
#include <cstdint>

#define NN 100000
#define DD 128
#define EE_MAX 1700000

// Scratch (allocation-free rule: __device__ globals)
__device__ float g_agg[(size_t)NN * DD];
__device__ float g_h1[(size_t)NN * DD];
__device__ __nv_bfloat16 g_xbf[(size_t)NN * DD];
__device__ __nv_bfloat16 g_h1bf[(size_t)NN * DD];
__device__ int   g_deg[NN];
__device__ int   g_cursor[NN];
__device__ int   g_rowptr[NN + 1];
__device__ int   g_col[EE_MAX];
__device__ int   g_partial[128];
__device__ int   g_total;
__device__ float g_wcat[2][256 * DD];   // [layer][k(0..255)][o(0..127)]
__device__ float g_bias[2][DD];

// ---------------------------------------------------------------------------
__global__ void zero_int2_kernel(int* __restrict__ a, int* __restrict__ b, int n) {
    int i = blockIdx.x * blockDim.x + threadIdx.x;
    if (i < n) { a[i] = 0; b[i] = 0; }
}

__global__ void deg_kernel(const int* __restrict__ dst, int E) {
    int e = blockIdx.x * blockDim.x + threadIdx.x;
    if (e < E) atomicAdd(&g_deg[dst[e]], 1);
}

// fp32 -> bf16 feature cache (each thread: 4 elems)
__global__ void cvt_bf16_kernel(const float* __restrict__ in,
                                __nv_bfloat16* __restrict__ out, int n4) {
    int i = blockIdx.x * blockDim.x + threadIdx.x;
    if (i < n4) {
        float4 v = ((const float4*)in)[i];
        __nv_bfloat162 a = __floats2bfloat162_rn(v.x, v.y);
        __nv_bfloat162 b = __floats2bfloat162_rn(v.z, v.w);
        uint2 u;
        u.x = *(uint32_t*)&a;
        u.y = *(uint32_t*)&b;
        ((uint2*)out)[i] = u;
    }
}

// --- three-phase exclusive scan of g_deg -> g_rowptr -----------------------
__global__ __launch_bounds__(1024) void scanA_kernel(int n) {
    const int i = blockIdx.x * 1024 + threadIdx.x;
    const int lane = threadIdx.x & 31;
    const int w = threadIdx.x >> 5;
    const int v = (i < n) ? g_deg[i] : 0;
    int s = v;
#pragma unroll
    for (int o = 1; o < 32; o <<= 1) {
        int t = __shfl_up_sync(0xffffffffu, s, o);
        if (lane >= o) s += t;
    }
    __shared__ int wsum[32];
    if (lane == 31) wsum[w] = s;
    __syncthreads();
    if (w == 0) {
        int ws = wsum[lane];
#pragma unroll
        for (int o = 1; o < 32; o <<= 1) {
            int t = __shfl_up_sync(0xffffffffu, ws, o);
            if (lane >= o) ws += t;
        }
        wsum[lane] = ws;
    }
    __syncthreads();
    const int excl = s - v + (w ? wsum[w - 1] : 0);
    if (i < n) g_rowptr[i] = excl;
    if (threadIdx.x == 1023) g_partial[blockIdx.x] = excl + v;
}

__global__ __launch_bounds__(128) void scanB_kernel(int nb) {
    __shared__ int s[128];
    const int t = threadIdx.x;
    s[t] = (t < nb) ? g_partial[t] : 0;
    __syncthreads();
    for (int o = 1; o < 128; o <<= 1) {
        int x = (t >= o) ? s[t - o] : 0;
        __syncthreads();
        s[t] += x;
        __syncthreads();
    }
    g_partial[t] = t ? s[t - 1] : 0;
    if (t == 127) g_total = s[127];
}

__global__ void scanC_kernel(int n) {
    int i = blockIdx.x * blockDim.x + threadIdx.x;
    if (i < n) g_rowptr[i] += g_partial[i >> 10];
    if (i == n) g_rowptr[n] = g_total;
}

__global__ void fill_kernel(const int* __restrict__ src, const int* __restrict__ dst, int E) {
    int e = blockIdx.x * blockDim.x + threadIdx.x;
    if (e < E) {
        int d = dst[e];
        int p = atomicAdd(&g_cursor[d], 1);
        g_col[g_rowptr[d] + p] = src[e];
    }
}

__global__ void prep_w_kernel(const float* __restrict__ Wn1, const float* __restrict__ bn1,
                              const float* __restrict__ Ws1, const float* __restrict__ bs1,
                              const float* __restrict__ Wn2, const float* __restrict__ bn2,
                              const float* __restrict__ Ws2, const float* __restrict__ bs2) {
    int idx = blockIdx.x * blockDim.x + threadIdx.x;
    if (idx < 256 * DD) {
        int k = idx / DD, o = idx % DD;
        g_wcat[0][idx] = (k < DD) ? Wn1[o * DD + k] : Ws1[o * DD + (k - DD)];
        g_wcat[1][idx] = (k < DD) ? Wn2[o * DD + k] : Ws2[o * DD + (k - DD)];
    }
    if (idx < DD) {
        g_bias[0][idx] = bn1[idx] + bs1[idx];
        g_bias[1][idx] = bn2[idx] + bs2[idx];
    }
}

// ---------------------------------------------------------------------------
// Gather-side mean aggregation over bf16 features: one warp per node.
// 32 lanes x 4 features (8B loads). fp32 accumulation, pre-normalized output.
__global__ __launch_bounds__(256) void agg_kernel(const __nv_bfloat16* __restrict__ feat,
                                                  float* __restrict__ out, int n) {
    const int warp = (blockIdx.x * blockDim.x + threadIdx.x) >> 5;
    if (warp >= n) return;
    const int lane = threadIdx.x & 31;
    const int c = lane << 2;
    const int beg = g_rowptr[warp];
    const int end = g_rowptr[warp + 1];

    float ax = 0.f, ay = 0.f, az = 0.f, aw = 0.f;
    for (int base = beg; base < end; base += 32) {
        const int idx = base + lane;
        const int sv = (idx < end) ? g_col[idx] : 0;
        const int cnt = min(end - base, 32);
#pragma unroll 4
        for (int j = 0; j < cnt; j++) {
            const int s = __shfl_sync(0xffffffffu, sv, j);
            const uint2 u = *(const uint2*)(feat + (size_t)s * DD + c);
            const float2 p0 = __bfloat1622float2(*(const __nv_bfloat162*)&u.x);
            const float2 p1 = __bfloat1622float2(*(const __nv_bfloat162*)&u.y);
            ax += p0.x; ay += p0.y; az += p1.x; aw += p1.y;
        }
    }
    const float inv = 1.0f / fmaxf((float)(end - beg), 1.0f);
    float4 r;
    r.x = ax * inv; r.y = ay * inv; r.z = az * inv; r.w = aw * inv;
    *(float4*)(out + (size_t)warp * DD + c) = r;
}

// ---------------------------------------------------------------------------
// Fused SGEMM with packed fp32x2 FMA (FFMA2).
// out[r][o] = relu?( [agg|A2][r][:] @ Wcat[:,o] + bias[o] ),  K=256
// Optionally dual-writes a bf16 copy of the output (feature cache for layer 2).
template <bool RELU, bool WBF>
__global__ __launch_bounds__(256) void gemm_kernel(const float* __restrict__ A2,
                                                   const float* __restrict__ Wcat,
                                                   const float* __restrict__ bias,
                                                   float* __restrict__ out,
                                                   __nv_bfloat16* __restrict__ outbf,
                                                   int n) {
    __shared__ float As[8][128];
    __shared__ float Bs[8][128];

    const int tid = threadIdx.x;
    const int block_row = blockIdx.x * 128;

    const int a_row = tid >> 1;            // 0..127
    const int a_k   = (tid & 1) << 2;      // 0 or 4
    const int g_row = block_row + a_row;
    const bool row_ok = g_row < n;
    const float* a1p = g_agg + (size_t)g_row * DD;
    const float* a2p = A2 + (size_t)g_row * DD;

    const int b_k   = tid >> 5;            // 0..7
    const int b_col = (tid & 31) << 2;     // 0..124

    const int tr = (tid >> 4) << 3;
    const int tc = (tid & 15) << 3;

    unsigned long long acc[8][4];          // 4x f32x2 per row (8 cols)
#pragma unroll
    for (int i = 0; i < 8; i++)
#pragma unroll
        for (int j = 0; j < 4; j++) acc[i][j] = 0ull;

    for (int k0 = 0; k0 < 256; k0 += 8) {
        float4 av = make_float4(0.f, 0.f, 0.f, 0.f);
        const int kk = k0 + a_k;
        if (row_ok) {
            av = (kk < 128) ? *(const float4*)(a1p + kk)
                            : *(const float4*)(a2p + (kk - 128));
        }
        const float4 bv = *(const float4*)(Wcat + (size_t)(k0 + b_k) * 128 + b_col);

        if (k0) __syncthreads();
        As[a_k + 0][a_row] = av.x;
        As[a_k + 1][a_row] = av.y;
        As[a_k + 2][a_row] = av.z;
        As[a_k + 3][a_row] = av.w;
        *(float4*)&Bs[b_k][b_col] = bv;
        __syncthreads();

#pragma unroll
        for (int p = 0; p < 8; p++) {
            float ar[8];
            unsigned long long br[4];
#pragma unroll
            for (int i = 0; i < 8; i++) ar[i] = As[p][tr + i];
            const unsigned long long* bp =
                (const unsigned long long*)&Bs[p][tc];
#pragma unroll
            for (int j = 0; j < 4; j++) br[j] = bp[j];
#pragma unroll
            for (int i = 0; i < 8; i++) {
                unsigned long long a2;
                asm("mov.b64 %0, {%1, %1};" : "=l"(a2) : "f"(ar[i]));
#pragma unroll
                for (int j = 0; j < 4; j++) {
                    asm("fma.rn.f32x2 %0, %1, %2, %0;"
                        : "+l"(acc[i][j]) : "l"(a2), "l"(br[j]));
                }
            }
        }
    }

    float bb[8];
#pragma unroll
    for (int j = 0; j < 8; j++) bb[j] = bias[tc + j];

#pragma unroll
    for (int i = 0; i < 8; i++) {
        int r = block_row + tr + i;
        if (r < n) {
            float v[8];
#pragma unroll
            for (int j = 0; j < 4; j++) {
                float lo, hi;
                asm("mov.b64 {%0, %1}, %2;" : "=f"(lo), "=f"(hi) : "l"(acc[i][j]));
                v[2 * j]     = lo + bb[2 * j];
                v[2 * j + 1] = hi + bb[2 * j + 1];
                if (RELU) {
                    v[2 * j]     = fmaxf(v[2 * j], 0.f);
                    v[2 * j + 1] = fmaxf(v[2 * j + 1], 0.f);
                }
            }
            float* op = out + (size_t)r * DD + tc;
            *(float4*)(op)     = make_float4(v[0], v[1], v[2], v[3]);
            *(float4*)(op + 4) = make_float4(v[4], v[5], v[6], v[7]);
            if (WBF) {
                __nv_bfloat162 c0 = __floats2bfloat162_rn(v[0], v[1]);
                __nv_bfloat162 c1 = __floats2bfloat162_rn(v[2], v[3]);
                __nv_bfloat162 c2 = __floats2bfloat162_rn(v[4], v[5]);
                __nv_bfloat162 c3 = __floats2bfloat162_rn(v[6], v[7]);
                uint4 u;
                u.x = *(uint32_t*)&c0; u.y = *(uint32_t*)&c1;
                u.z = *(uint32_t*)&c2; u.w = *(uint32_t*)&c3;
                *(uint4*)(outbf + (size_t)r * DD + tc) = u;
            }
        }
    }
}

// ---------------------------------------------------------------------------
extern "C" void kernel_launch(void* const* d_in, const int* in_sizes, int n_in,
                              void* d_out, int out_size) {
    const float* x   = (const float*)d_in[0];
    const int* ei    = (const int*)d_in[1];
    const float* Wn1 = (const float*)d_in[2];
    const float* bn1 = (const float*)d_in[3];
    const float* Ws1 = (const float*)d_in[4];
    const float* bs1 = (const float*)d_in[5];
    const float* Wn2 = (const float*)d_in[6];
    const float* bn2 = (const float*)d_in[7];
    const float* Ws2 = (const float*)d_in[8];
    const float* bs2 = (const float*)d_in[9];
    float* out = (float*)d_out;

    const int n = in_sizes[0] / DD;
    const int E = in_sizes[1] / 2;
    const int* src = ei;
    const int* dst = ei + E;

    float* d_h1;    cudaGetSymbolAddress((void**)&d_h1, g_h1);
    float* d_agg;   cudaGetSymbolAddress((void**)&d_agg, g_agg);
    __nv_bfloat16* d_xbf;  cudaGetSymbolAddress((void**)&d_xbf, g_xbf);
    __nv_bfloat16* d_h1bf; cudaGetSymbolAddress((void**)&d_h1bf, g_h1bf);
    int* d_deg;     cudaGetSymbolAddress((void**)&d_deg, g_deg);
    int* d_cursor;  cudaGetSymbolAddress((void**)&d_cursor, g_cursor);
    float* d_wcat0; cudaGetSymbolAddress((void**)&d_wcat0, g_wcat);
    float* d_bias0; cudaGetSymbolAddress((void**)&d_bias0, g_bias);

    const int threads = 256;
    const int nb = (n + 1023) / 1024;
    const int n4 = (n * DD) / 4;

    // --- CSR build + feature cache ---
    zero_int2_kernel<<<(n + threads - 1) / threads, threads>>>(d_deg, d_cursor, n);
    prep_w_kernel<<<(256 * DD + threads - 1) / threads, threads>>>(Wn1, bn1, Ws1, bs1,
                                                                   Wn2, bn2, Ws2, bs2);
    cvt_bf16_kernel<<<(n4 + threads - 1) / threads, threads>>>(x, d_xbf, n4);
    deg_kernel<<<(E + threads - 1) / threads, threads>>>(dst, E);
    scanA_kernel<<<nb, 1024>>>(n);
    scanB_kernel<<<1, 128>>>(nb);
    scanC_kernel<<<(n + 1 + threads - 1) / threads, threads>>>(n);
    fill_kernel<<<(E + threads - 1) / threads, threads>>>(src, dst, E);

    const unsigned agg_threads_total = (unsigned)n * 32u;
    const unsigned agg_blocks = (agg_threads_total + threads - 1) / threads;

    // layer 1: mean-aggregate x_bf16 -> agg, fused GEMM + relu -> h1 (+h1 bf16)
    agg_kernel<<<agg_blocks, threads>>>(d_xbf, d_agg, n);
    gemm_kernel<true, true><<<(n + 127) / 128, 256>>>(x, d_wcat0, d_bias0,
                                                      d_h1, d_h1bf, n);

    // layer 2: mean-aggregate h1_bf16 -> agg, fused GEMM -> out
    agg_kernel<<<agg_blocks, threads>>>(d_h1bf, d_agg, n);
    gemm_kernel<false, false><<<(n + 127) / 128, 256>>>(d_h1, d_wcat0 + 256 * DD,
                                                        d_bias0 + DD, out, nullptr, n);
}

// round 6
// speedup vs baseline: 1.5573x; 1.5573x over previous
#include <cuda_runtime.h>
#include <cstdint>

#define NN 100000
#define DD 128
#define EE_MAX 1700000

// Scratch (allocation-free rule: __device__ globals)
__device__ float g_agg[(size_t)NN * DD];
__device__ float g_h1[(size_t)NN * DD];
__device__ int   g_deg[NN];
__device__ int   g_cursor[NN];
__device__ int   g_rowptr[NN + 1];
__device__ int   g_col[EE_MAX];
__device__ int   g_partial[128];
__device__ int   g_total;
__device__ float g_wcat[2][256 * DD];   // [layer][k(0..255)][o(0..127)]
__device__ float g_bias[2][DD];

// ---------------------------------------------------------------------------
__global__ void zero_int2_kernel(int* __restrict__ a, int* __restrict__ b, int n) {
    int i = blockIdx.x * blockDim.x + threadIdx.x;
    if (i < n) { a[i] = 0; b[i] = 0; }
}

__global__ void deg_kernel(const int* __restrict__ dst, int E) {
    int e = blockIdx.x * blockDim.x + threadIdx.x;
    if (e < E) atomicAdd(&g_deg[dst[e]], 1);
}

// --- three-phase exclusive scan of g_deg -> g_rowptr -----------------------
__global__ __launch_bounds__(1024) void scanA_kernel(int n) {
    const int i = blockIdx.x * 1024 + threadIdx.x;
    const int lane = threadIdx.x & 31;
    const int w = threadIdx.x >> 5;
    const int v = (i < n) ? g_deg[i] : 0;
    int s = v;
#pragma unroll
    for (int o = 1; o < 32; o <<= 1) {
        int t = __shfl_up_sync(0xffffffffu, s, o);
        if (lane >= o) s += t;
    }
    __shared__ int wsum[32];
    if (lane == 31) wsum[w] = s;
    __syncthreads();
    if (w == 0) {
        int ws = wsum[lane];
#pragma unroll
        for (int o = 1; o < 32; o <<= 1) {
            int t = __shfl_up_sync(0xffffffffu, ws, o);
            if (lane >= o) ws += t;
        }
        wsum[lane] = ws;
    }
    __syncthreads();
    const int excl = s - v + (w ? wsum[w - 1] : 0);
    if (i < n) g_rowptr[i] = excl;
    if (threadIdx.x == 1023) g_partial[blockIdx.x] = excl + v;
}

__global__ __launch_bounds__(128) void scanB_kernel(int nb) {
    __shared__ int s[128];
    const int t = threadIdx.x;
    s[t] = (t < nb) ? g_partial[t] : 0;
    __syncthreads();
    for (int o = 1; o < 128; o <<= 1) {
        int x = (t >= o) ? s[t - o] : 0;
        __syncthreads();
        s[t] += x;
        __syncthreads();
    }
    g_partial[t] = t ? s[t - 1] : 0;
    if (t == 127) g_total = s[127];
}

__global__ void scanC_kernel(int n) {
    int i = blockIdx.x * blockDim.x + threadIdx.x;
    if (i < n) g_rowptr[i] += g_partial[i >> 10];
    if (i == n) g_rowptr[n] = g_total;
}

__global__ void fill_kernel(const int* __restrict__ src, const int* __restrict__ dst, int E) {
    int e = blockIdx.x * blockDim.x + threadIdx.x;
    if (e < E) {
        int d = dst[e];
        int p = atomicAdd(&g_cursor[d], 1);
        g_col[g_rowptr[d] + p] = src[e];
    }
}

__global__ void prep_w_kernel(const float* __restrict__ Wn1, const float* __restrict__ bn1,
                              const float* __restrict__ Ws1, const float* __restrict__ bs1,
                              const float* __restrict__ Wn2, const float* __restrict__ bn2,
                              const float* __restrict__ Ws2, const float* __restrict__ bs2) {
    int idx = blockIdx.x * blockDim.x + threadIdx.x;
    if (idx < 256 * DD) {
        int k = idx / DD, o = idx % DD;
        g_wcat[0][idx] = (k < DD) ? Wn1[o * DD + k] : Ws1[o * DD + (k - DD)];
        g_wcat[1][idx] = (k < DD) ? Wn2[o * DD + k] : Ws2[o * DD + (k - DD)];
    }
    if (idx < DD) {
        g_bias[0][idx] = bn1[idx] + bs1[idx];
        g_bias[1][idx] = bn2[idx] + bs2[idx];
    }
}

// ---------------------------------------------------------------------------
// Gather-side mean aggregation: one warp per node, pre-normalized by 1/deg.
// Inner loop per neighbor: SHFL + LDG.128 + 2x add.rn.f32x2 (packed fp32 adds).
__global__ __launch_bounds__(256) void agg_kernel(const float* __restrict__ feat,
                                                  float* __restrict__ out, int n) {
    const int warp = (blockIdx.x * blockDim.x + threadIdx.x) >> 5;
    if (warp >= n) return;
    const int lane = threadIdx.x & 31;
    const int c = lane << 2;
    const int beg = g_rowptr[warp];
    const int end = g_rowptr[warp + 1];

    unsigned long long a01 = 0ull, a23 = 0ull;   // packed f32x2 accumulators
    for (int base = beg; base < end; base += 32) {
        const int idx = base + lane;
        const int sv = (idx < end) ? g_col[idx] : 0;
        const int cnt = min(end - base, 32);
#pragma unroll 4
        for (int j = 0; j < cnt; j++) {
            const int s = __shfl_sync(0xffffffffu, sv, j);
            const ulonglong2 v = *(const ulonglong2*)(feat + (size_t)s * DD + c);
            asm("add.rn.f32x2 %0, %0, %1;" : "+l"(a01) : "l"(v.x));
            asm("add.rn.f32x2 %0, %0, %1;" : "+l"(a23) : "l"(v.y));
        }
    }
    const float inv = 1.0f / fmaxf((float)(end - beg), 1.0f);
    float4 r;
    asm("mov.b64 {%0, %1}, %2;" : "=f"(r.x), "=f"(r.y) : "l"(a01));
    asm("mov.b64 {%0, %1}, %2;" : "=f"(r.z), "=f"(r.w) : "l"(a23));
    r.x *= inv; r.y *= inv; r.z *= inv; r.w *= inv;
    *(float4*)(out + (size_t)warp * DD + c) = r;
}

// ---------------------------------------------------------------------------
// Fused SGEMM with packed fp32x2 FMA (FFMA2).
// out[r][o] = relu?( [agg|A2][r][:] @ Wcat[:,o] + bias[o] ),  K=256
// Tile: BM=128, BN=128, BK=8; 256 threads; per-thread 8 rows x 4 float2 cols.
template <bool RELU>
__global__ __launch_bounds__(256) void gemm_kernel(const float* __restrict__ A2,
                                                   const float* __restrict__ Wcat,
                                                   const float* __restrict__ bias,
                                                   float* __restrict__ out, int n) {
    __shared__ float As[8][128];
    __shared__ float Bs[8][128];

    const int tid = threadIdx.x;
    const int block_row = blockIdx.x * 128;

    const int a_row = tid >> 1;            // 0..127
    const int a_k   = (tid & 1) << 2;      // 0 or 4
    const int g_row = block_row + a_row;
    const bool row_ok = g_row < n;
    const float* a1p = g_agg + (size_t)g_row * DD;
    const float* a2p = A2 + (size_t)g_row * DD;

    const int b_k   = tid >> 5;            // 0..7
    const int b_col = (tid & 31) << 2;     // 0..124

    const int tr = (tid >> 4) << 3;
    const int tc = (tid & 15) << 3;

    unsigned long long acc[8][4];          // 4x f32x2 per row (8 cols)
#pragma unroll
    for (int i = 0; i < 8; i++)
#pragma unroll
        for (int j = 0; j < 4; j++) acc[i][j] = 0ull;

    for (int k0 = 0; k0 < 256; k0 += 8) {
        float4 av = make_float4(0.f, 0.f, 0.f, 0.f);
        const int kk = k0 + a_k;
        if (row_ok) {
            av = (kk < 128) ? *(const float4*)(a1p + kk)
                            : *(const float4*)(a2p + (kk - 128));
        }
        const float4 bv = *(const float4*)(Wcat + (size_t)(k0 + b_k) * 128 + b_col);

        if (k0) __syncthreads();
        As[a_k + 0][a_row] = av.x;
        As[a_k + 1][a_row] = av.y;
        As[a_k + 2][a_row] = av.z;
        As[a_k + 3][a_row] = av.w;
        *(float4*)&Bs[b_k][b_col] = bv;
        __syncthreads();

#pragma unroll
        for (int p = 0; p < 8; p++) {
            float ar[8];
            unsigned long long br[4];
#pragma unroll
            for (int i = 0; i < 8; i++) ar[i] = As[p][tr + i];
            const unsigned long long* bp =
                (const unsigned long long*)&Bs[p][tc];
#pragma unroll
            for (int j = 0; j < 4; j++) br[j] = bp[j];
#pragma unroll
            for (int i = 0; i < 8; i++) {
                unsigned long long a2;
                asm("mov.b64 %0, {%1, %1};" : "=l"(a2) : "f"(ar[i]));
#pragma unroll
                for (int j = 0; j < 4; j++) {
                    asm("fma.rn.f32x2 %0, %1, %2, %0;"
                        : "+l"(acc[i][j]) : "l"(a2), "l"(br[j]));
                }
            }
        }
    }

    float bb[8];
#pragma unroll
    for (int j = 0; j < 8; j++) bb[j] = bias[tc + j];

#pragma unroll
    for (int i = 0; i < 8; i++) {
        int r = block_row + tr + i;
        if (r < n) {
            float v[8];
#pragma unroll
            for (int j = 0; j < 4; j++) {
                float lo, hi;
                asm("mov.b64 {%0, %1}, %2;" : "=f"(lo), "=f"(hi) : "l"(acc[i][j]));
                v[2 * j]     = lo + bb[2 * j];
                v[2 * j + 1] = hi + bb[2 * j + 1];
                if (RELU) {
                    v[2 * j]     = fmaxf(v[2 * j], 0.f);
                    v[2 * j + 1] = fmaxf(v[2 * j + 1], 0.f);
                }
            }
            float* op = out + (size_t)r * DD + tc;
            *(float4*)(op)     = make_float4(v[0], v[1], v[2], v[3]);
            *(float4*)(op + 4) = make_float4(v[4], v[5], v[6], v[7]);
        }
    }
}

// ---------------------------------------------------------------------------
extern "C" void kernel_launch(void* const* d_in, const int* in_sizes, int n_in,
                              void* d_out, int out_size) {
    const float* x   = (const float*)d_in[0];
    const int* ei    = (const int*)d_in[1];
    const float* Wn1 = (const float*)d_in[2];
    const float* bn1 = (const float*)d_in[3];
    const float* Ws1 = (const float*)d_in[4];
    const float* bs1 = (const float*)d_in[5];
    const float* Wn2 = (const float*)d_in[6];
    const float* bn2 = (const float*)d_in[7];
    const float* Ws2 = (const float*)d_in[8];
    const float* bs2 = (const float*)d_in[9];
    float* out = (float*)d_out;

    const int n = in_sizes[0] / DD;
    const int E = in_sizes[1] / 2;
    const int* src = ei;
    const int* dst = ei + E;

    float* d_h1;    cudaGetSymbolAddress((void**)&d_h1, g_h1);
    float* d_agg;   cudaGetSymbolAddress((void**)&d_agg, g_agg);
    int* d_deg;     cudaGetSymbolAddress((void**)&d_deg, g_deg);
    int* d_cursor;  cudaGetSymbolAddress((void**)&d_cursor, g_cursor);
    float* d_wcat0; cudaGetSymbolAddress((void**)&d_wcat0, g_wcat);
    float* d_bias0; cudaGetSymbolAddress((void**)&d_bias0, g_bias);

    const int threads = 256;
    const int nb = (n + 1023) / 1024;

    // --- CSR build ---
    zero_int2_kernel<<<(n + threads - 1) / threads, threads>>>(d_deg, d_cursor, n);
    prep_w_kernel<<<(256 * DD + threads - 1) / threads, threads>>>(Wn1, bn1, Ws1, bs1,
                                                                   Wn2, bn2, Ws2, bs2);
    deg_kernel<<<(E + threads - 1) / threads, threads>>>(dst, E);
    scanA_kernel<<<nb, 1024>>>(n);
    scanB_kernel<<<1, 128>>>(nb);
    scanC_kernel<<<(n + 1 + threads - 1) / threads, threads>>>(n);
    fill_kernel<<<(E + threads - 1) / threads, threads>>>(src, dst, E);

    const unsigned agg_threads_total = (unsigned)n * 32u;
    const unsigned agg_blocks = (agg_threads_total + threads - 1) / threads;

    // layer 1: mean-aggregate x -> agg, fused GEMM + relu -> h1
    agg_kernel<<<agg_blocks, threads>>>(x, d_agg, n);
    gemm_kernel<true><<<(n + 127) / 128, 256>>>(x, d_wcat0, d_bias0, d_h1, n);

    // layer 2: mean-aggregate h1 -> agg, fused GEMM -> out
    agg_kernel<<<agg_blocks, threads>>>(d_h1, d_agg, n);
    gemm_kernel<false><<<(n + 127) / 128, 256>>>(d_h1, d_wcat0 + 256 * DD, d_bias0 + DD,
                                                 out, n);
}

// round 7
// speedup vs baseline: 1.7267x; 1.1087x over previous
#include <cuda_runtime.h>
#include <cstdint>

#define NN 100000
#define DD 128
#define EE_MAX 1700000

// Scratch (allocation-free rule: __device__ globals)
__device__ float g_agg[(size_t)NN * DD];
__device__ float g_h1[(size_t)NN * DD];
__device__ int   g_deg[NN];
__device__ int   g_cursor[NN];
__device__ int   g_rowptr[NN + 1];
__device__ int   g_col[EE_MAX];
__device__ int   g_partial[128];
__device__ int   g_total;

// ---------------------------------------------------------------------------
__global__ void zero_int2_kernel(int* __restrict__ a, int* __restrict__ b, int n) {
    int i = blockIdx.x * blockDim.x + threadIdx.x;
    if (i < n) { a[i] = 0; b[i] = 0; }
}

__global__ void deg_kernel(const int* __restrict__ dst, int E) {
    int e = blockIdx.x * blockDim.x + threadIdx.x;
    if (e < E) atomicAdd(&g_deg[dst[e]], 1);
}

// --- three-phase exclusive scan of g_deg -> g_rowptr -----------------------
__global__ __launch_bounds__(1024) void scanA_kernel(int n) {
    const int i = blockIdx.x * 1024 + threadIdx.x;
    const int lane = threadIdx.x & 31;
    const int w = threadIdx.x >> 5;
    const int v = (i < n) ? g_deg[i] : 0;
    int s = v;
#pragma unroll
    for (int o = 1; o < 32; o <<= 1) {
        int t = __shfl_up_sync(0xffffffffu, s, o);
        if (lane >= o) s += t;
    }
    __shared__ int wsum[32];
    if (lane == 31) wsum[w] = s;
    __syncthreads();
    if (w == 0) {
        int ws = wsum[lane];
#pragma unroll
        for (int o = 1; o < 32; o <<= 1) {
            int t = __shfl_up_sync(0xffffffffu, ws, o);
            if (lane >= o) ws += t;
        }
        wsum[lane] = ws;
    }
    __syncthreads();
    const int excl = s - v + (w ? wsum[w - 1] : 0);
    if (i < n) g_rowptr[i] = excl;
    if (threadIdx.x == 1023) g_partial[blockIdx.x] = excl + v;
}

__global__ __launch_bounds__(128) void scanB_kernel(int nb) {
    __shared__ int s[128];
    const int t = threadIdx.x;
    s[t] = (t < nb) ? g_partial[t] : 0;
    __syncthreads();
    for (int o = 1; o < 128; o <<= 1) {
        int x = (t >= o) ? s[t - o] : 0;
        __syncthreads();
        s[t] += x;
        __syncthreads();
    }
    g_partial[t] = t ? s[t - 1] : 0;
    if (t == 127) g_total = s[127];
}

__global__ void scanC_kernel(int n) {
    int i = blockIdx.x * blockDim.x + threadIdx.x;
    if (i < n) g_rowptr[i] += g_partial[i >> 10];
    if (i == n) g_rowptr[n] = g_total;
}

__global__ void fill_kernel(const int* __restrict__ src, const int* __restrict__ dst, int E) {
    int e = blockIdx.x * blockDim.x + threadIdx.x;
    if (e < E) {
        int d = dst[e];
        int p = atomicAdd(&g_cursor[d], 1);
        g_col[g_rowptr[d] + p] = src[e];
    }
}

// ---------------------------------------------------------------------------
// Gather-side mean aggregation: one warp per node, pre-normalized by 1/deg.
__global__ __launch_bounds__(256) void agg_kernel(const float* __restrict__ feat,
                                                  float* __restrict__ out, int n) {
    const int warp = (blockIdx.x * blockDim.x + threadIdx.x) >> 5;
    if (warp >= n) return;
    const int lane = threadIdx.x & 31;
    const int c = lane << 2;
    const int beg = g_rowptr[warp];
    const int end = g_rowptr[warp + 1];

    unsigned long long a01 = 0ull, a23 = 0ull;
    for (int base = beg; base < end; base += 32) {
        const int idx = base + lane;
        const int sv = (idx < end) ? g_col[idx] : 0;
        const int cnt = min(end - base, 32);
#pragma unroll 4
        for (int j = 0; j < cnt; j++) {
            const int s = __shfl_sync(0xffffffffu, sv, j);
            const ulonglong2 v = *(const ulonglong2*)(feat + (size_t)s * DD + c);
            asm("add.rn.f32x2 %0, %0, %1;" : "+l"(a01) : "l"(v.x));
            asm("add.rn.f32x2 %0, %0, %1;" : "+l"(a23) : "l"(v.y));
        }
    }
    const float inv = 1.0f / fmaxf((float)(end - beg), 1.0f);
    float4 r;
    asm("mov.b64 {%0, %1}, %2;" : "=f"(r.x), "=f"(r.y) : "l"(a01));
    asm("mov.b64 {%0, %1}, %2;" : "=f"(r.z), "=f"(r.w) : "l"(a23));
    r.x *= inv; r.y *= inv; r.z *= inv; r.w *= inv;
    *(float4*)(out + (size_t)warp * DD + c) = r;
}

// ---------------------------------------------------------------------------
// 3xTF32 mma.sync GEMM, fused bias(+relu).
// out[r][o] = relu?( sum_k<128 agg[r][k]*Wn[o][k] + sum_k A2[r][k]*Ws[o][k]
//                    + bn[o] + bs[o] )
// CTA: 128x128xK256, 8 warps (2m x 4n), warp tile 64x32, K chunks of 32.
// A and B split into tf32 hi/lo in-kernel during SMEM staging.
// SMEM tile layout: [k4 (0..7)][row 0..128 (pad 129)][c 0..3] floats.
__device__ __forceinline__ void f32_split_tf32(float a, uint32_t& hi, uint32_t& lo) {
    asm("cvt.rna.tf32.f32 %0, %1;" : "=r"(hi) : "f"(a));
    float hf = __uint_as_float(hi);
    asm("cvt.rna.tf32.f32 %0, %1;" : "=r"(lo) : "f"(a - hf));
}
__device__ __forceinline__ void mma_tf32(float* d, const uint32_t* a, const uint32_t* b) {
    asm volatile(
        "mma.sync.aligned.m16n8k8.row.col.f32.tf32.tf32.f32 "
        "{%0,%1,%2,%3}, {%4,%5,%6,%7}, {%8,%9}, {%0,%1,%2,%3};"
        : "+f"(d[0]), "+f"(d[1]), "+f"(d[2]), "+f"(d[3])
        : "r"(a[0]), "r"(a[1]), "r"(a[2]), "r"(a[3]), "r"(b[0]), "r"(b[1]));
}

static constexpr int TILEF = 8 * 129 * 4;                 // floats per smem tile
static constexpr int GEMM_SMEM = 4 * TILEF * 4;           // bytes

template <bool RELU>
__global__ __launch_bounds__(256) void gemm_mma_kernel(
    const float* __restrict__ A2, const float* __restrict__ Wn,
    const float* __restrict__ Ws, const float* __restrict__ bn,
    const float* __restrict__ bs, float* __restrict__ out, int n) {
    extern __shared__ float dsm[];
    float* sAhi = dsm;
    float* sAlo = dsm + TILEF;
    float* sBhi = dsm + 2 * TILEF;
    float* sBlo = dsm + 3 * TILEF;

    const int tid = threadIdx.x;
    const int wid = tid >> 5;
    const int lane = tid & 31;
    const int g = lane >> 2;       // group row 0..7
    const int c = lane & 3;        // col-in-group 0..3
    const int block_row = blockIdx.x * 128;
    const int m0 = (wid >> 2) * 64;
    const int n0 = (wid & 3) * 32;

    float acc[4][4][4];
#pragma unroll
    for (int mt = 0; mt < 4; mt++)
#pragma unroll
        for (int nt = 0; nt < 4; nt++)
#pragma unroll
            for (int q = 0; q < 4; q++) acc[mt][nt][q] = 0.f;

    for (int c0 = 0; c0 < 256; c0 += 32) {
        const float* aptr = (c0 < 128) ? g_agg + (size_t)block_row * DD + c0
                                       : A2 + (size_t)block_row * DD + (c0 - 128);
        const float* bptr = (c0 < 128) ? (Wn + c0) : (Ws + (c0 - 128));

        if (c0) __syncthreads();
#pragma unroll
        for (int i = 0; i < 4; i++) {
            const int f = i * 256 + tid;          // 0..1023
            const int row = f >> 3;               // 0..127
            const int k4 = f & 7;
            const int so = k4 * 516 + row * 4;    // smem float offset

            float4 va = make_float4(0.f, 0.f, 0.f, 0.f);
            if (block_row + row < n) va = *(const float4*)(aptr + (size_t)row * DD + k4 * 4);
            uint4 h, l;
            f32_split_tf32(va.x, h.x, l.x);
            f32_split_tf32(va.y, h.y, l.y);
            f32_split_tf32(va.z, h.z, l.z);
            f32_split_tf32(va.w, h.w, l.w);
            *(uint4*)(sAhi + so) = h;
            *(uint4*)(sAlo + so) = l;

            const float4 vb = *(const float4*)(bptr + (size_t)row * 128 + k4 * 4);
            f32_split_tf32(vb.x, h.x, l.x);
            f32_split_tf32(vb.y, h.y, l.y);
            f32_split_tf32(vb.z, h.z, l.z);
            f32_split_tf32(vb.w, h.w, l.w);
            *(uint4*)(sBhi + so) = h;
            *(uint4*)(sBlo + so) = l;
        }
        __syncthreads();

#pragma unroll
        for (int s = 0; s < 4; s++) {
            const int kA = 2 * s, kB = 2 * s + 1;
            uint32_t Ah[4][4], Al[4][4], Bh[4][2], Bl[4][2];
#pragma unroll
            for (int mt = 0; mt < 4; mt++) {
                const int r0 = m0 + mt * 16 + g;
                const int i00 = kA * 516 + r0 * 4 + c;
                const int i10 = kB * 516 + r0 * 4 + c;
                Ah[mt][0] = __float_as_uint(sAhi[i00]);
                Ah[mt][1] = __float_as_uint(sAhi[i00 + 32]);
                Ah[mt][2] = __float_as_uint(sAhi[i10]);
                Ah[mt][3] = __float_as_uint(sAhi[i10 + 32]);
                Al[mt][0] = __float_as_uint(sAlo[i00]);
                Al[mt][1] = __float_as_uint(sAlo[i00 + 32]);
                Al[mt][2] = __float_as_uint(sAlo[i10]);
                Al[mt][3] = __float_as_uint(sAlo[i10 + 32]);
            }
#pragma unroll
            for (int nt = 0; nt < 4; nt++) {
                const int nn = n0 + nt * 8 + g;
                const int j0 = kA * 516 + nn * 4 + c;
                const int j1 = kB * 516 + nn * 4 + c;
                Bh[nt][0] = __float_as_uint(sBhi[j0]);
                Bh[nt][1] = __float_as_uint(sBhi[j1]);
                Bl[nt][0] = __float_as_uint(sBlo[j0]);
                Bl[nt][1] = __float_as_uint(sBlo[j1]);
            }
#pragma unroll
            for (int mt = 0; mt < 4; mt++)
#pragma unroll
                for (int nt = 0; nt < 4; nt++) {
                    mma_tf32(acc[mt][nt], Ah[mt], Bh[nt]);
                    mma_tf32(acc[mt][nt], Ah[mt], Bl[nt]);
                    mma_tf32(acc[mt][nt], Al[mt], Bh[nt]);
                }
        }
    }

    // Epilogue: bias + optional relu, float2 stores
#pragma unroll
    for (int nt = 0; nt < 4; nt++) {
        const int col = n0 + nt * 8 + 2 * c;
        const float b0v = bn[col] + bs[col];
        const float b1v = bn[col + 1] + bs[col + 1];
#pragma unroll
        for (int mt = 0; mt < 4; mt++) {
            const int r = block_row + m0 + mt * 16 + g;
            float v0 = acc[mt][nt][0] + b0v;
            float v1 = acc[mt][nt][1] + b1v;
            float v2 = acc[mt][nt][2] + b0v;
            float v3 = acc[mt][nt][3] + b1v;
            if (RELU) {
                v0 = fmaxf(v0, 0.f); v1 = fmaxf(v1, 0.f);
                v2 = fmaxf(v2, 0.f); v3 = fmaxf(v3, 0.f);
            }
            if (r < n)     *(float2*)(out + (size_t)r * DD + col) = make_float2(v0, v1);
            if (r + 8 < n) *(float2*)(out + (size_t)(r + 8) * DD + col) = make_float2(v2, v3);
        }
    }
}

// ---------------------------------------------------------------------------
extern "C" void kernel_launch(void* const* d_in, const int* in_sizes, int n_in,
                              void* d_out, int out_size) {
    const float* x   = (const float*)d_in[0];
    const int* ei    = (const int*)d_in[1];
    const float* Wn1 = (const float*)d_in[2];
    const float* bn1 = (const float*)d_in[3];
    const float* Ws1 = (const float*)d_in[4];
    const float* bs1 = (const float*)d_in[5];
    const float* Wn2 = (const float*)d_in[6];
    const float* bn2 = (const float*)d_in[7];
    const float* Ws2 = (const float*)d_in[8];
    const float* bs2 = (const float*)d_in[9];
    float* out = (float*)d_out;

    const int n = in_sizes[0] / DD;
    const int E = in_sizes[1] / 2;
    const int* src = ei;
    const int* dst = ei + E;

    float* d_h1;    cudaGetSymbolAddress((void**)&d_h1, g_h1);
    float* d_agg;   cudaGetSymbolAddress((void**)&d_agg, g_agg);
    int* d_deg;     cudaGetSymbolAddress((void**)&d_deg, g_deg);
    int* d_cursor;  cudaGetSymbolAddress((void**)&d_cursor, g_cursor);

    cudaFuncSetAttribute(gemm_mma_kernel<true>,
                         cudaFuncAttributeMaxDynamicSharedMemorySize, GEMM_SMEM);
    cudaFuncSetAttribute(gemm_mma_kernel<false>,
                         cudaFuncAttributeMaxDynamicSharedMemorySize, GEMM_SMEM);

    const int threads = 256;
    const int nb = (n + 1023) / 1024;

    // --- CSR build ---
    zero_int2_kernel<<<(n + threads - 1) / threads, threads>>>(d_deg, d_cursor, n);
    deg_kernel<<<(E + threads - 1) / threads, threads>>>(dst, E);
    scanA_kernel<<<nb, 1024>>>(n);
    scanB_kernel<<<1, 128>>>(nb);
    scanC_kernel<<<(n + 1 + threads - 1) / threads, threads>>>(n);
    fill_kernel<<<(E + threads - 1) / threads, threads>>>(src, dst, E);

    const unsigned agg_threads_total = (unsigned)n * 32u;
    const unsigned agg_blocks = (agg_threads_total + threads - 1) / threads;
    const int gemm_blocks = (n + 127) / 128;

    // layer 1: mean-aggregate x -> agg, mma GEMM + bias + relu -> h1
    agg_kernel<<<agg_blocks, threads>>>(x, d_agg, n);
    gemm_mma_kernel<true><<<gemm_blocks, 256, GEMM_SMEM>>>(
        x, Wn1, Ws1, bn1, bs1, d_h1, n);

    // layer 2: mean-aggregate h1 -> agg, mma GEMM + bias -> out
    agg_kernel<<<agg_blocks, threads>>>(d_h1, d_agg, n);
    gemm_mma_kernel<false><<<gemm_blocks, 256, GEMM_SMEM>>>(
        d_h1, Wn2, Ws2, bn2, bs2, out, n);
}

// round 8
// speedup vs baseline: 2.4323x; 1.4086x over previous
#include <cuda_runtime.h>
#include <cstdint>

#define NN 100000
#define DD 128
#define EE_MAX 1700000

// Scratch (allocation-free rule: __device__ globals)
__device__ float g_agg[(size_t)NN * DD];
__device__ float g_h1[(size_t)NN * DD];
__device__ int   g_deg[NN];
__device__ int   g_cursor[NN];
__device__ int   g_rowptr[NN + 1];
__device__ int   g_col[EE_MAX];
__device__ int   g_partial[128];
__device__ int   g_total;

// ---------------------------------------------------------------------------
__global__ void zero_int2_kernel(int* __restrict__ a, int* __restrict__ b, int n) {
    int i = blockIdx.x * blockDim.x + threadIdx.x;
    if (i < n) { a[i] = 0; b[i] = 0; }
}

__global__ void deg_kernel(const int* __restrict__ dst, int E) {
    int e = blockIdx.x * blockDim.x + threadIdx.x;
    if (e < E) atomicAdd(&g_deg[dst[e]], 1);
}

// --- three-phase exclusive scan of g_deg -> g_rowptr -----------------------
__global__ __launch_bounds__(1024) void scanA_kernel(int n) {
    const int i = blockIdx.x * 1024 + threadIdx.x;
    const int lane = threadIdx.x & 31;
    const int w = threadIdx.x >> 5;
    const int v = (i < n) ? g_deg[i] : 0;
    int s = v;
#pragma unroll
    for (int o = 1; o < 32; o <<= 1) {
        int t = __shfl_up_sync(0xffffffffu, s, o);
        if (lane >= o) s += t;
    }
    __shared__ int wsum[32];
    if (lane == 31) wsum[w] = s;
    __syncthreads();
    if (w == 0) {
        int ws = wsum[lane];
#pragma unroll
        for (int o = 1; o < 32; o <<= 1) {
            int t = __shfl_up_sync(0xffffffffu, ws, o);
            if (lane >= o) ws += t;
        }
        wsum[lane] = ws;
    }
    __syncthreads();
    const int excl = s - v + (w ? wsum[w - 1] : 0);
    if (i < n) g_rowptr[i] = excl;
    if (threadIdx.x == 1023) g_partial[blockIdx.x] = excl + v;
}

__global__ __launch_bounds__(128) void scanB_kernel(int nb) {
    __shared__ int s[128];
    const int t = threadIdx.x;
    s[t] = (t < nb) ? g_partial[t] : 0;
    __syncthreads();
    for (int o = 1; o < 128; o <<= 1) {
        int x = (t >= o) ? s[t - o] : 0;
        __syncthreads();
        s[t] += x;
        __syncthreads();
    }
    g_partial[t] = t ? s[t - 1] : 0;
    if (t == 127) g_total = s[127];
}

__global__ void scanC_kernel(int n) {
    int i = blockIdx.x * blockDim.x + threadIdx.x;
    if (i < n) g_rowptr[i] += g_partial[i >> 10];
    if (i == n) g_rowptr[n] = g_total;
}

__global__ void fill_kernel(const int* __restrict__ src, const int* __restrict__ dst, int E) {
    int e = blockIdx.x * blockDim.x + threadIdx.x;
    if (e < E) {
        int d = dst[e];
        int p = atomicAdd(&g_cursor[d], 1);
        g_col[g_rowptr[d] + p] = src[e];
    }
}

// ---------------------------------------------------------------------------
// Gather-side mean aggregation: one warp per node, pre-normalized by 1/deg.
__global__ __launch_bounds__(256) void agg_kernel(const float* __restrict__ feat,
                                                  float* __restrict__ out, int n) {
    const int warp = (blockIdx.x * blockDim.x + threadIdx.x) >> 5;
    if (warp >= n) return;
    const int lane = threadIdx.x & 31;
    const int c = lane << 2;
    const int beg = g_rowptr[warp];
    const int end = g_rowptr[warp + 1];

    unsigned long long a01 = 0ull, a23 = 0ull;
    for (int base = beg; base < end; base += 32) {
        const int idx = base + lane;
        const int sv = (idx < end) ? g_col[idx] : 0;
        const int cnt = min(end - base, 32);
#pragma unroll 4
        for (int j = 0; j < cnt; j++) {
            const int s = __shfl_sync(0xffffffffu, sv, j);
            const ulonglong2 v = *(const ulonglong2*)(feat + (size_t)s * DD + c);
            asm("add.rn.f32x2 %0, %0, %1;" : "+l"(a01) : "l"(v.x));
            asm("add.rn.f32x2 %0, %0, %1;" : "+l"(a23) : "l"(v.y));
        }
    }
    const float inv = 1.0f / fmaxf((float)(end - beg), 1.0f);
    float4 r;
    asm("mov.b64 {%0, %1}, %2;" : "=f"(r.x), "=f"(r.y) : "l"(a01));
    asm("mov.b64 {%0, %1}, %2;" : "=f"(r.z), "=f"(r.w) : "l"(a23));
    r.x *= inv; r.y *= inv; r.z *= inv; r.w *= inv;
    *(float4*)(out + (size_t)warp * DD + c) = r;
}

// ---------------------------------------------------------------------------
// Single-pass TF32 mma.sync GEMM, fused bias(+relu).
// out[r][o] = relu?( sum_k<128 agg[r][k]*Wn[o][k] + sum_k A2[r][k]*Ws[o][k]
//                    + bn[o] + bs[o] )
// CTA: 128x128xK256, 8 warps (2m x 4n), warp tile 64x32, K chunks of 32.
// Operands rounded to tf32 (cvt.rna) during SMEM staging.
// SMEM tile layout: [k4 (0..7)][row 0..128 (pad 129)][c 0..3] floats.
__device__ __forceinline__ uint32_t f32_to_tf32(float a) {
    uint32_t r;
    asm("cvt.rna.tf32.f32 %0, %1;" : "=r"(r) : "f"(a));
    return r;
}
__device__ __forceinline__ void mma_tf32(float* d, const uint32_t* a, const uint32_t* b) {
    asm volatile(
        "mma.sync.aligned.m16n8k8.row.col.f32.tf32.tf32.f32 "
        "{%0,%1,%2,%3}, {%4,%5,%6,%7}, {%8,%9}, {%0,%1,%2,%3};"
        : "+f"(d[0]), "+f"(d[1]), "+f"(d[2]), "+f"(d[3])
        : "r"(a[0]), "r"(a[1]), "r"(a[2]), "r"(a[3]), "r"(b[0]), "r"(b[1]));
}

static constexpr int TILEF = 8 * 129 * 4;                 // floats per smem tile
static constexpr int GEMM_SMEM = 2 * TILEF * 4;           // bytes (A + B)

template <bool RELU>
__global__ __launch_bounds__(256) void gemm_mma_kernel(
    const float* __restrict__ A2, const float* __restrict__ Wn,
    const float* __restrict__ Ws, const float* __restrict__ bn,
    const float* __restrict__ bs, float* __restrict__ out, int n) {
    extern __shared__ float dsm[];
    float* sA = dsm;
    float* sB = dsm + TILEF;

    const int tid = threadIdx.x;
    const int wid = tid >> 5;
    const int lane = tid & 31;
    const int g = lane >> 2;       // group row 0..7
    const int c = lane & 3;        // col-in-group 0..3
    const int block_row = blockIdx.x * 128;
    const int m0 = (wid >> 2) * 64;
    const int n0 = (wid & 3) * 32;

    float acc[4][4][4];
#pragma unroll
    for (int mt = 0; mt < 4; mt++)
#pragma unroll
        for (int nt = 0; nt < 4; nt++)
#pragma unroll
            for (int q = 0; q < 4; q++) acc[mt][nt][q] = 0.f;

    for (int c0 = 0; c0 < 256; c0 += 32) {
        const float* aptr = (c0 < 128) ? g_agg + (size_t)block_row * DD + c0
                                       : A2 + (size_t)block_row * DD + (c0 - 128);
        const float* bptr = (c0 < 128) ? (Wn + c0) : (Ws + (c0 - 128));

        if (c0) __syncthreads();
#pragma unroll
        for (int i = 0; i < 4; i++) {
            const int f = i * 256 + tid;          // 0..1023
            const int row = f >> 3;               // 0..127
            const int k4 = f & 7;
            const int so = k4 * 516 + row * 4;    // smem float offset

            float4 va = make_float4(0.f, 0.f, 0.f, 0.f);
            if (block_row + row < n) va = *(const float4*)(aptr + (size_t)row * DD + k4 * 4);
            uint4 h;
            h.x = f32_to_tf32(va.x);
            h.y = f32_to_tf32(va.y);
            h.z = f32_to_tf32(va.z);
            h.w = f32_to_tf32(va.w);
            *(uint4*)(sA + so) = h;

            const float4 vb = *(const float4*)(bptr + (size_t)row * 128 + k4 * 4);
            h.x = f32_to_tf32(vb.x);
            h.y = f32_to_tf32(vb.y);
            h.z = f32_to_tf32(vb.z);
            h.w = f32_to_tf32(vb.w);
            *(uint4*)(sB + so) = h;
        }
        __syncthreads();

#pragma unroll
        for (int s = 0; s < 4; s++) {
            const int kA = 2 * s, kB = 2 * s + 1;
            uint32_t Ah[4][4], Bh[4][2];
#pragma unroll
            for (int mt = 0; mt < 4; mt++) {
                const int r0 = m0 + mt * 16 + g;
                const int i00 = kA * 516 + r0 * 4 + c;
                const int i10 = kB * 516 + r0 * 4 + c;
                Ah[mt][0] = __float_as_uint(sA[i00]);
                Ah[mt][1] = __float_as_uint(sA[i00 + 32]);
                Ah[mt][2] = __float_as_uint(sA[i10]);
                Ah[mt][3] = __float_as_uint(sA[i10 + 32]);
            }
#pragma unroll
            for (int nt = 0; nt < 4; nt++) {
                const int nn = n0 + nt * 8 + g;
                Bh[nt][0] = __float_as_uint(sB[kA * 516 + nn * 4 + c]);
                Bh[nt][1] = __float_as_uint(sB[kB * 516 + nn * 4 + c]);
            }
#pragma unroll
            for (int mt = 0; mt < 4; mt++)
#pragma unroll
                for (int nt = 0; nt < 4; nt++)
                    mma_tf32(acc[mt][nt], Ah[mt], Bh[nt]);
        }
    }

    // Epilogue: bias + optional relu, float2 stores
#pragma unroll
    for (int nt = 0; nt < 4; nt++) {
        const int col = n0 + nt * 8 + 2 * c;
        const float b0v = bn[col] + bs[col];
        const float b1v = bn[col + 1] + bs[col + 1];
#pragma unroll
        for (int mt = 0; mt < 4; mt++) {
            const int r = block_row + m0 + mt * 16 + g;
            float v0 = acc[mt][nt][0] + b0v;
            float v1 = acc[mt][nt][1] + b1v;
            float v2 = acc[mt][nt][2] + b0v;
            float v3 = acc[mt][nt][3] + b1v;
            if (RELU) {
                v0 = fmaxf(v0, 0.f); v1 = fmaxf(v1, 0.f);
                v2 = fmaxf(v2, 0.f); v3 = fmaxf(v3, 0.f);
            }
            if (r < n)     *(float2*)(out + (size_t)r * DD + col) = make_float2(v0, v1);
            if (r + 8 < n) *(float2*)(out + (size_t)(r + 8) * DD + col) = make_float2(v2, v3);
        }
    }
}

// ---------------------------------------------------------------------------
extern "C" void kernel_launch(void* const* d_in, const int* in_sizes, int n_in,
                              void* d_out, int out_size) {
    const float* x   = (const float*)d_in[0];
    const int* ei    = (const int*)d_in[1];
    const float* Wn1 = (const float*)d_in[2];
    const float* bn1 = (const float*)d_in[3];
    const float* Ws1 = (const float*)d_in[4];
    const float* bs1 = (const float*)d_in[5];
    const float* Wn2 = (const float*)d_in[6];
    const float* bn2 = (const float*)d_in[7];
    const float* Ws2 = (const float*)d_in[8];
    const float* bs2 = (const float*)d_in[9];
    float* out = (float*)d_out;

    const int n = in_sizes[0] / DD;
    const int E = in_sizes[1] / 2;
    const int* src = ei;
    const int* dst = ei + E;

    float* d_h1;    cudaGetSymbolAddress((void**)&d_h1, g_h1);
    float* d_agg;   cudaGetSymbolAddress((void**)&d_agg, g_agg);
    int* d_deg;     cudaGetSymbolAddress((void**)&d_deg, g_deg);
    int* d_cursor;  cudaGetSymbolAddress((void**)&d_cursor, g_cursor);

    cudaFuncSetAttribute(gemm_mma_kernel<true>,
                         cudaFuncAttributeMaxDynamicSharedMemorySize, GEMM_SMEM);
    cudaFuncSetAttribute(gemm_mma_kernel<false>,
                         cudaFuncAttributeMaxDynamicSharedMemorySize, GEMM_SMEM);

    const int threads = 256;
    const int nb = (n + 1023) / 1024;

    // --- CSR build ---
    zero_int2_kernel<<<(n + threads - 1) / threads, threads>>>(d_deg, d_cursor, n);
    deg_kernel<<<(E + threads - 1) / threads, threads>>>(dst, E);
    scanA_kernel<<<nb, 1024>>>(n);
    scanB_kernel<<<1, 128>>>(nb);
    scanC_kernel<<<(n + 1 + threads - 1) / threads, threads>>>(n);
    fill_kernel<<<(E + threads - 1) / threads, threads>>>(src, dst, E);

    const unsigned agg_threads_total = (unsigned)n * 32u;
    const unsigned agg_blocks = (agg_threads_total + threads - 1) / threads;
    const int gemm_blocks = (n + 127) / 128;

    // layer 1: mean-aggregate x -> agg, mma GEMM + bias + relu -> h1
    agg_kernel<<<agg_blocks, threads>>>(x, d_agg, n);
    gemm_mma_kernel<true><<<gemm_blocks, 256, GEMM_SMEM>>>(
        x, Wn1, Ws1, bn1, bs1, d_h1, n);

    // layer 2: mean-aggregate h1 -> agg, mma GEMM + bias -> out
    agg_kernel<<<agg_blocks, threads>>>(d_h1, d_agg, n);
    gemm_mma_kernel<false><<<gemm_blocks, 256, GEMM_SMEM>>>(
        d_h1, Wn2, Ws2, bn2, bs2, out, n);
}